// round 13
// baseline (speedup 1.0000x reference)
#include <cuda_runtime.h>
#include <cuda_fp16.h>
#include <cstdint>

#define NCELL 500000
#define MNET  450000
#define EKE   2000000
#define ESE   500000
#define ECOMB (EKE + ESE)
#define EMB   64
#define VN    64
#define NL    3
#define CATD  256
#define OUTD  8
#define NODE_MASK 0x7FFFF
#define SCAN_TOT (MNET + NCELL)

// ---------------- scratch ----------------
__device__ int   g_cnt_n[NCELL];
__device__ int   g_cnt_e[MNET];
__device__ int   g_cnt_comb[MNET];
__device__ int   g_off_net[MNET + 1];
__device__ int   g_cur_net[MNET];
__device__ int   g_off_node[NCELL + 1];
__device__ int   g_cur_node[NCELL];
__device__ int2  g_csr_net[ECOMB];     // (node | batch<<19 | (net&63)<<25, weight bits)
__device__ int2  g_csr_node[EKE];      // (net, weight bits)
__device__ int   g_partial[1024];
__device__ float g_rsq_n[NCELL];
__device__ float g_rsq_e[MNET];
__device__ float g_cat[(size_t)NCELL * CATD];
__device__ float g_net[(size_t)MNET * EMB];
__device__ __half g_cath[(size_t)NCELL * EMB];   // fp16 mirror of current cat layer slice
__device__ __half g_neth[(size_t)MNET * EMB];    // fp16 mirror of h_net
__device__ float g_vn[VN * EMB];
__device__ float g_pool[VN * EMB];   // invariant: zero at kernel_launch entry
__device__ float g_cntvn[VN];

// ---------------- helpers ----------------
__device__ __forceinline__ uint32_t f2tf32(float v) {
    uint32_t r; asm("cvt.rna.tf32.f32 %0, %1;" : "=r"(r) : "f"(v)); return r;
}
__device__ __forceinline__ void split_tf32(float v, uint32_t& hi, uint32_t& lo) {
    hi = f2tf32(v);
    lo = f2tf32(v - __uint_as_float(hi));
}
__device__ __forceinline__ void mma_tf32(float* c, uint32_t a0, uint32_t a1, uint32_t a2,
                                         uint32_t a3, uint32_t b0, uint32_t b1) {
    asm("mma.sync.aligned.m16n8k8.row.col.f32.tf32.tf32.f32 "
        "{%0,%1,%2,%3},{%4,%5,%6,%7},{%8,%9},{%0,%1,%2,%3};"
        : "+f"(c[0]), "+f"(c[1]), "+f"(c[2]), "+f"(c[3])
        : "r"(a0), "r"(a1), "r"(a2), "r"(a3), "r"(b0), "r"(b1));
}

// ---------------- setup ----------------
__global__ void k_zero_all() {
    int i = blockIdx.x * blockDim.x + threadIdx.x;
    if (i < NCELL) g_cnt_n[i] = 0;
    if (i < MNET) { g_cnt_e[i] = 0; g_cnt_comb[i] = 0; }
    if (i < VN) g_cntvn[i] = 0.f;
}
__global__ void k_count(const int* __restrict__ sn, const int* __restrict__ se,
                        const int* __restrict__ src_net) {
    int i = blockIdx.x * blockDim.x + threadIdx.x;
    if (i < EKE) { atomicAdd(&g_cnt_n[sn[i]], 1); atomicAdd(&g_cnt_e[se[i]], 1); }
    if (i < ESE) atomicAdd(&g_cnt_comb[src_net[i]], 1);
}
__global__ void k_prep(const int* __restrict__ batch, const float* __restrict__ vn_emb) {
    __shared__ float hist[VN];
    int tid = threadIdx.x;
    int i = blockIdx.x * blockDim.x + tid;
    if (tid < VN) hist[tid] = 0.f;
    __syncthreads();
    if (i < MNET) {
        int ce = g_cnt_e[i];
        g_cnt_comb[i] += ce;
        g_rsq_e[i] = rsqrtf(fmaxf((float)ce, 1.f));
    }
    if (i < NCELL) {
        g_rsq_n[i] = rsqrtf(fmaxf((float)g_cnt_n[i], 1.f));
        atomicAdd(&hist[batch[i]], 1.f);
    }
    if (i < VN * EMB) g_vn[i] = vn_emb[i & 63];
    __syncthreads();
    if (tid < VN) atomicAdd(&g_cntvn[tid], hist[tid]);
}

// ---------------- combined exclusive scan over [cnt_comb | cnt_n] ----------------
__device__ __forceinline__ int comb_cnt(int i) {
    return (i < MNET) ? g_cnt_comb[i] : g_cnt_n[i - MNET];
}
__global__ void k_scan1() {
    __shared__ int s[256];
    int base = blockIdx.x * 1024, t = threadIdx.x;
    int sum = 0;
    #pragma unroll
    for (int q = 0; q < 4; q++) { int i = base + q * 256 + t; sum += (i < SCAN_TOT) ? comb_cnt(i) : 0; }
    s[t] = sum; __syncthreads();
    for (int st = 128; st > 0; st >>= 1) {
        if (t < st) s[t] += s[t + st];
        __syncthreads();
    }
    if (t == 0) g_partial[blockIdx.x] = s[0];
}
__global__ void k_scan2(int nb) {
    __shared__ int s[1024];
    int t = threadIdx.x;
    int v = (t < nb) ? g_partial[t] : 0;
    s[t] = v; __syncthreads();
    for (int st = 1; st < 1024; st <<= 1) {
        int a = (t >= st) ? s[t - st] : 0;
        __syncthreads();
        s[t] += a; __syncthreads();
    }
    if (t < nb) g_partial[t] = s[t] - v;
}
__global__ void k_scan3() {
    __shared__ int s[256];
    int t = threadIdx.x, base = blockIdx.x * 1024;
    int v[4], sum = 0;
    #pragma unroll
    for (int q = 0; q < 4; q++) { int i = base + t * 4 + q; v[q] = (i < SCAN_TOT) ? comb_cnt(i) : 0; sum += v[q]; }
    s[t] = sum; __syncthreads();
    int mine = sum;
    for (int st = 1; st < 256; st <<= 1) {
        int a = (t >= st) ? s[t - st] : 0;
        __syncthreads();
        s[t] += a; __syncthreads();
    }
    int ex = s[t] - mine + g_partial[blockIdx.x];
    #pragma unroll
    for (int q = 0; q < 4; q++) {
        int i = base + t * 4 + q;
        if (i < SCAN_TOT) {
            if (i < MNET) { g_off_net[i] = ex; g_cur_net[i] = ex; }
            else { g_off_node[i - MNET] = ex - ECOMB; g_cur_node[i - MNET] = ex - ECOMB; }
            ex += v[q];
        }
    }
    if (blockIdx.x == 0 && t == 0) {
        g_off_net[MNET] = ECOMB;
        g_off_node[NCELL] = EKE;
    }
}

// ---------------- combined CSR scatter (net entries carry local row idx in bits 25..30) ----------------
__global__ void k_scat(const int* __restrict__ sink_node, const int* __restrict__ sink_net,
                       const int* __restrict__ src_node, const int* __restrict__ src_net,
                       const int* __restrict__ batch) {
    int e = blockIdx.x * blockDim.x + threadIdx.x;
    if (e < EKE) {
        int node = sink_node[e], net = sink_net[e];
        float ew = g_rsq_n[node] * g_rsq_e[net];
        int packed = node | (batch[node] << 19) | ((net & 63) << 25);
        int pn = atomicAdd(&g_cur_net[net], 1);
        g_csr_net[pn] = make_int2(packed, __float_as_int(ew));
        int pd = atomicAdd(&g_cur_node[node], 1);
        g_csr_node[pd] = make_int2(net, __float_as_int(ew));
    }
    if (e < ESE) {
        int node = src_node[e], net = src_net[e];
        int packed = node | (batch[node] << 19) | ((net & 63) << 25);
        int pos = atomicAdd(&g_cur_net[net], 1);
        g_csr_net[pos] = make_int2(packed, __float_as_int(1.f));
    }
}

// ---------------- persistent embedding (+ optional fused VN pooling, fp16 mirror) ----------------
#define EMB_GRID 592
__global__ __launch_bounds__(256) void k_embed(
    const float* __restrict__ feat, const float* __restrict__ w, const float* __restrict__ b,
    float* __restrict__ out, int nrows, int ostride,
    int doPool, const int* __restrict__ batch, __half* __restrict__ mirror) {
    __shared__ float s_w[16 * EMB];
    __shared__ float s_in[32][17];
    __shared__ int   s_batch[32];
    __shared__ float s_pool[VN * EMB];
    int tid = threadIdx.x;
    int j = tid & 63, rq = tid >> 6;

    for (int i = tid; i < 16 * EMB; i += 256) s_w[i] = w[i];
    if (doPool) for (int i = tid; i < VN * EMB; i += 256) s_pool[i] = 0.f;
    float breg = b[j];
    __syncthreads();
    float wreg[16];
    #pragma unroll
    for (int k = 0; k < 16; k++) wreg[k] = s_w[k * EMB + j];

    int ntiles = (nrows + 31) / 32;
    for (int tile = blockIdx.x; tile < ntiles; tile += gridDim.x) {
        int base = tile * 32;
        __syncthreads();
        if (tid < 128) {
            int r = tid >> 2, k4 = tid & 3;
            int row = base + r;
            float4 v = (row < nrows) ? ((const float4*)feat)[(size_t)row * 4 + k4]
                                     : make_float4(0.f, 0.f, 0.f, 0.f);
            s_in[r][k4 * 4 + 0] = v.x; s_in[r][k4 * 4 + 1] = v.y;
            s_in[r][k4 * 4 + 2] = v.z; s_in[r][k4 * 4 + 3] = v.w;
        }
        if (doPool && tid < 32) {
            int row = base + tid;
            s_batch[tid] = (row < nrows) ? batch[row] : 0;
        }
        __syncthreads();
        #pragma unroll
        for (int s = 0; s < 8; s++) {
            int r = rq + s * 4;
            int row = base + r;
            if (row < nrows) {
                float a = breg;
                #pragma unroll
                for (int k = 0; k < 16; k++) a += s_in[r][k] * wreg[k];
                a = fmaxf(a, 0.f);
                out[(size_t)row * ostride + j] = a;
                if (mirror) mirror[(size_t)row * EMB + j] = __float2half_rn(a);
                if (doPool) atomicAdd(&s_pool[s_batch[r] * EMB + j], a);
            }
        }
    }
    if (doPool) {
        __syncthreads();
        for (int i = tid; i < VN * EMB; i += 256) atomicAdd(&g_pool[i], s_pool[i]);
    }
}

// ---------------- VN pooling from cat ----------------
__global__ void k_pool_cat(const int* __restrict__ batch, int l) {
    __shared__ float s[VN * EMB];
    int tid = threadIdx.x;
    for (int i = tid; i < VN * EMB; i += 256) s[i] = 0.f;
    __syncthreads();
    int c0 = (tid & 15) * 4, r = tid >> 4;
    for (long long n = (long long)blockIdx.x * 16 + r; n < NCELL; n += (long long)gridDim.x * 16) {
        int b = batch[n];
        float4 v = *(const float4*)&g_cat[n * CATD + l * EMB + c0];
        atomicAdd(&s[b * EMB + c0 + 0], v.x);
        atomicAdd(&s[b * EMB + c0 + 1], v.y);
        atomicAdd(&s[b * EMB + c0 + 2], v.z);
        atomicAdd(&s[b * EMB + c0 + 3], v.w);
    }
    __syncthreads();
    for (int i = tid; i < VN * EMB; i += 256) atomicAdd(&g_pool[i], s[i]);
}

// ---------------- VN update (re-zeros g_pool) ----------------
__global__ void k_vn(const float* __restrict__ w, const float* __restrict__ b) {
    int v = blockIdx.x, j = threadIdx.x;
    __shared__ float t[EMB];
    float cnt = g_cntvn[v];
    float vv = g_vn[v * EMB + j];
    t[j] = (g_pool[v * EMB + j] + cnt * vv) / fmaxf(cnt, 1.f) + vv;
    g_pool[v * EMB + j] = 0.f;
    __syncthreads();
    float acc = b[j];
    #pragma unroll
    for (int k = 0; k < EMB; k++) acc += t[k] * w[k * EMB + j];
    g_vn[v * EMB + j] = vv + fmaxf(acc, 0.f);
}

// =====================================================================
// Conv kernels: 3xTF32 mma epilogue (per-tile W split, as R11)
// =====================================================================
#define CLD 68
#define DSMEM_NET  ((64 * CLD + 64 * CLD + VN * EMB + EMB) * 4)   // ~51 KB
#define DSMEM_NODE ((64 * CLD + 64 * CLD + EMB) * 4)              // ~35 KB
#define CONV_GRID 592
#define NTILES_NET  ((MNET + 63) / 64)
#define NTILES_NODE ((NCELL + 63) / 64)

__device__ __forceinline__ void conv_mma_epilogue(
    float* As, float* Ws, const float* sb,
    int tid, long long row0, int nrows, float* __restrict__ outbuf,
    int ostride4, int ooff4, __half* __restrict__ mirror)
{
    int warp = tid >> 5, lane = tid & 31;
    int gid = lane >> 2, tig = lane & 3;
    int mrow0 = (warp >> 1) * 16;
    int ncol0 = (warp & 1) * 32;

    float c[4][4];
    #pragma unroll
    for (int nt = 0; nt < 4; nt++)
        #pragma unroll
        for (int q = 0; q < 4; q++) c[nt][q] = 0.f;

    #pragma unroll
    for (int kk = 0; kk < 8; kk++) {
        int kb = kk * 8;
        uint32_t ah0, al0, ah1, al1, ah2, al2, ah3, al3;
        split_tf32(As[(mrow0 + gid) * CLD + kb + tig], ah0, al0);
        split_tf32(As[(mrow0 + gid + 8) * CLD + kb + tig], ah1, al1);
        split_tf32(As[(mrow0 + gid) * CLD + kb + tig + 4], ah2, al2);
        split_tf32(As[(mrow0 + gid + 8) * CLD + kb + tig + 4], ah3, al3);
        #pragma unroll
        for (int nt = 0; nt < 4; nt++) {
            int col = ncol0 + nt * 8 + gid;
            uint32_t bh0, bl0, bh1, bl1;
            split_tf32(Ws[(kb + tig) * CLD + col], bh0, bl0);
            split_tf32(Ws[(kb + tig + 4) * CLD + col], bh1, bl1);
            mma_tf32(c[nt], ah0, ah1, ah2, ah3, bh0, bh1);
            mma_tf32(c[nt], ah0, ah1, ah2, ah3, bl0, bl1);
            mma_tf32(c[nt], al0, al1, al2, al3, bh0, bh1);
        }
    }
    __syncthreads();
    #pragma unroll
    for (int nt = 0; nt < 4; nt++) {
        int col0 = ncol0 + nt * 8 + 2 * tig;
        float b0 = sb[col0], b1 = sb[col0 + 1];
        As[(mrow0 + gid) * CLD + col0]     = fmaxf(c[nt][0] + b0, 0.f);
        As[(mrow0 + gid) * CLD + col0 + 1] = fmaxf(c[nt][1] + b1, 0.f);
        As[(mrow0 + gid + 8) * CLD + col0]     = fmaxf(c[nt][2] + b0, 0.f);
        As[(mrow0 + gid + 8) * CLD + col0 + 1] = fmaxf(c[nt][3] + b1, 0.f);
    }
    __syncthreads();
    #pragma unroll
    for (int q = 0; q < 4; q++) {
        int idx = q * 256 + tid;
        int r = idx >> 4, c4 = idx & 15;
        long long row = row0 + r;
        if (row < nrows) {
            float4 v = *(const float4*)(As + r * CLD + c4 * 4);
            ((float4*)outbuf)[row * ostride4 + ooff4 + c4] = v;
            union { __half2 h[2]; uint2 u; } pk;
            pk.h[0] = __floats2half2_rn(v.x, v.y);
            pk.h[1] = __floats2half2_rn(v.z, v.w);
            ((uint2*)mirror)[row * 16 + c4] = pk.u;
        }
    }
}

// ---- net conv: EDGE-PARALLEL gather (contiguous CSR range per 64-net tile) ----
__global__ __launch_bounds__(256) void k_net_mma(
    const float* __restrict__ W, const float* __restrict__ b, int l) {
    extern __shared__ float sm[];
    float* As = sm;
    float* Ws = sm + 64 * CLD;
    float* vns = sm + 128 * CLD;
    float* sb = vns + VN * EMB;
    int tid = threadIdx.x;
    for (int i = tid; i < EMB * EMB; i += 256) Ws[(i >> 6) * CLD + (i & 63)] = W[i];
    for (int i = tid; i < VN * EMB; i += 256) vns[i] = g_vn[i];
    if (tid < EMB) sb[tid] = b[tid];

    int warp = tid >> 5, lane = tid & 31;
    const __half2* cath2 = (const __half2*)g_cath;
    const float2* vn2 = (const float2*)vns;

    for (int tile = blockIdx.x; tile < NTILES_NET; tile += gridDim.x) {
        long long row0 = (long long)tile * 64;
        int rows = (int)(((row0 + 64) <= MNET) ? 64 : (MNET - row0));
        __syncthreads();
        // init As with net self-term (coalesced float4)
        #pragma unroll
        for (int q = 0; q < 4; q++) {
            int idx = q * 256 + tid;
            int r = idx >> 4, c4 = idx & 15;
            float4 v = (r < rows) ? ((const float4*)g_net)[(row0 + r) * 16 + c4]
                                  : make_float4(0.f, 0.f, 0.f, 0.f);
            *(float4*)(As + r * CLD + c4 * 4) = v;
        }
        __syncthreads();
        // edge-parallel accumulate
        int pstart = g_off_net[row0];
        int pend = g_off_net[row0 + rows];
        int p = pstart + warp;
        for (; p + 8 < pend; p += 16) {
            int2 e0 = g_csr_net[p];
            int2 e1 = g_csr_net[p + 8];
            int n0 = e0.x & NODE_MASK, b0 = (e0.x >> 19) & 63, c0 = (e0.x >> 25) & 63;
            int n1 = e1.x & NODE_MASK, b1 = (e1.x >> 19) & 63, c1 = (e1.x >> 25) & 63;
            float2 v0 = __half22float2(cath2[(size_t)n0 * 32 + lane]);
            float2 v1 = __half22float2(cath2[(size_t)n1 * 32 + lane]);
            float2 u0 = vn2[b0 * 32 + lane];
            float2 u1 = vn2[b1 * 32 + lane];
            float w0 = __int_as_float(e0.y), w1 = __int_as_float(e1.y);
            atomicAdd(&As[c0 * CLD + 2 * lane],     w0 * (v0.x + u0.x));
            atomicAdd(&As[c0 * CLD + 2 * lane + 1], w0 * (v0.y + u0.y));
            atomicAdd(&As[c1 * CLD + 2 * lane],     w1 * (v1.x + u1.x));
            atomicAdd(&As[c1 * CLD + 2 * lane + 1], w1 * (v1.y + u1.y));
        }
        if (p < pend) {
            int2 e0 = g_csr_net[p];
            int n0 = e0.x & NODE_MASK, b0 = (e0.x >> 19) & 63, c0 = (e0.x >> 25) & 63;
            float2 v0 = __half22float2(cath2[(size_t)n0 * 32 + lane]);
            float2 u0 = vn2[b0 * 32 + lane];
            float w0 = __int_as_float(e0.y);
            atomicAdd(&As[c0 * CLD + 2 * lane],     w0 * (v0.x + u0.x));
            atomicAdd(&As[c0 * CLD + 2 * lane + 1], w0 * (v0.y + u0.y));
        }
        __syncthreads();
        conv_mma_epilogue(As, Ws, sb, tid, row0, MNET, (float*)g_net, 16, 0, g_neth);
    }
}

// ---- node conv: row-per-warp gather (R11 control) ----
__global__ __launch_bounds__(256) void k_node_mma(
    const float* __restrict__ W, const float* __restrict__ b,
    const int* __restrict__ batch, int l) {
    extern __shared__ float sm[];
    float* As = sm;
    float* Ws = sm + 64 * CLD;
    float* sb = sm + 128 * CLD;
    int tid = threadIdx.x;
    for (int i = tid; i < EMB * EMB; i += 256) Ws[(i >> 6) * CLD + (i & 63)] = W[i];
    if (tid < EMB) sb[tid] = b[tid];

    int warp = tid >> 5, lane = tid & 31;
    const float2* cat2 = (const float2*)g_cat;
    const __half2* neth2 = (const __half2*)g_neth;
    const float2* vn2 = (const float2*)g_vn;

    for (int tile = blockIdx.x; tile < NTILES_NODE; tile += gridDim.x) {
        long long row0 = (long long)tile * 64;
        __syncthreads();
        for (int q = 0; q < 8; q++) {
            int r = warp * 8 + q;
            long long node = row0 + r;
            float2 acc = make_float2(0.f, 0.f);
            if (node < NCELL) {
                int bb = batch[node];
                float2 v = cat2[node * 128 + l * 32 + lane];
                float2 u = vn2[bb * 32 + lane];
                acc.x = v.x + u.x; acc.y = v.y + u.y;
                int p0 = g_off_node[node], p1 = g_off_node[node + 1];
                int p = p0;
                for (; p + 3 < p1; p += 4) {
                    int2 e0 = g_csr_node[p], e1 = g_csr_node[p + 1];
                    int2 e2 = g_csr_node[p + 2], e3 = g_csr_node[p + 3];
                    float2 v0 = __half22float2(neth2[(size_t)e0.x * 32 + lane]);
                    float2 v1 = __half22float2(neth2[(size_t)e1.x * 32 + lane]);
                    float2 v2 = __half22float2(neth2[(size_t)e2.x * 32 + lane]);
                    float2 v3 = __half22float2(neth2[(size_t)e3.x * 32 + lane]);
                    float w0 = __int_as_float(e0.y), w1 = __int_as_float(e1.y);
                    float w2 = __int_as_float(e2.y), w3 = __int_as_float(e3.y);
                    acc.x += w0 * v0.x + w1 * v1.x + w2 * v2.x + w3 * v3.x;
                    acc.y += w0 * v0.y + w1 * v1.y + w2 * v2.y + w3 * v3.y;
                }
                for (; p < p1; p++) {
                    int2 e0 = g_csr_node[p];
                    float2 v0 = __half22float2(neth2[(size_t)e0.x * 32 + lane]);
                    float w0 = __int_as_float(e0.y);
                    acc.x += w0 * v0.x; acc.y += w0 * v0.y;
                }
            }
            *(float2*)(As + r * CLD + 2 * lane) = acc;
        }
        __syncthreads();
        conv_mma_epilogue(As, Ws, sb, tid, row0, NCELL, (float*)g_cat, 64, (l + 1) * 16, g_cath);
    }
}

// ---------------- head: 128 rows x 256 cols, 512 threads ----------------
#define AS_LD 68
#define BS_LD 260
#define HS_LD 260
#define DSMEM_HEAD (128 * HS_LD * 4)

__global__ __launch_bounds__(512) void k_head_mma(
    const float* __restrict__ fc1w, const float* __restrict__ fc1b,
    const float* __restrict__ fc2w, const float* __restrict__ fc2b,
    const float* __restrict__ outw, const float* __restrict__ outb,
    const float* __restrict__ cat,
    float* __restrict__ nodes_out, float* __restrict__ ret_out) {
    extern __shared__ float sm[];
    float* As = sm;
    float* Bs = sm + 128 * AS_LD;
    float* Hs = sm;
    __shared__ float s_ow[CATD];
    __shared__ float s_fc2[8 * 256];
    __shared__ float rpart4[128][4];

    int tid = threadIdx.x;
    int warp = tid >> 5, lane = tid & 31;
    int gid = lane >> 2, tig = lane & 3;
    int mrow0 = (warp >> 2) * 32;
    int ncol0 = (warp & 3) * 64;
    size_t n0 = (size_t)blockIdx.x * 128;

    if (tid < CATD) s_ow[tid] = outw[tid];
    for (int i = tid; i < 2048; i += 512) {
        int o = i >> 8, jj = i & 255;
        s_fc2[o * 256 + jj] = fc2w[jj * 8 + o];
    }
    { int r = tid >> 2, q = tid & 3; rpart4[r][q] = 0.f; }

    float c[2][8][4];
    #pragma unroll
    for (int mf = 0; mf < 2; mf++)
        #pragma unroll
        for (int nt = 0; nt < 8; nt++)
            #pragma unroll
            for (int q = 0; q < 4; q++) c[mf][nt][q] = 0.f;

    for (int kc = 0; kc < 4; kc++) {
        __syncthreads();
        #pragma unroll
        for (int q = 0; q < 4; q++) {
            int idx = q * 512 + tid;
            int r = idx >> 4, k4 = idx & 15;
            size_t row = n0 + r;
            float4 v = (row < NCELL)
                ? *(const float4*)(cat + row * CATD + kc * 64 + k4 * 4)
                : make_float4(0.f, 0.f, 0.f, 0.f);
            *(float4*)(As + r * AS_LD + k4 * 4) = v;
        }
        #pragma unroll
        for (int q = 0; q < 8; q++) {
            int idx = q * 512 + tid;
            int r = idx >> 6, j4 = idx & 63;
            float4 v = *(const float4*)(fc1w + (size_t)(kc * 64 + r) * 256 + j4 * 4);
            *(float4*)(Bs + r * BS_LD + j4 * 4) = v;
        }
        __syncthreads();
        {
            int r = tid >> 2, q = tid & 3;
            float a = 0.f;
            #pragma unroll
            for (int kk = 0; kk < 16; kk++)
                a += As[r * AS_LD + q * 16 + kk] * s_ow[kc * 64 + q * 16 + kk];
            rpart4[r][q] += a;
        }
        #pragma unroll
        for (int kk = 0; kk < 8; kk++) {
            int kb = kk * 8;
            uint32_t a[2][4];
            #pragma unroll
            for (int mf = 0; mf < 2; mf++) {
                int rb = mrow0 + mf * 16;
                a[mf][0] = f2tf32(As[(rb + gid) * AS_LD + kb + tig]);
                a[mf][1] = f2tf32(As[(rb + gid + 8) * AS_LD + kb + tig]);
                a[mf][2] = f2tf32(As[(rb + gid) * AS_LD + kb + tig + 4]);
                a[mf][3] = f2tf32(As[(rb + gid + 8) * AS_LD + kb + tig + 4]);
            }
            #pragma unroll
            for (int nt = 0; nt < 8; nt++) {
                int col = ncol0 + nt * 8 + gid;
                uint32_t b0 = f2tf32(Bs[(kb + tig) * BS_LD + col]);
                uint32_t b1 = f2tf32(Bs[(kb + tig + 4) * BS_LD + col]);
                mma_tf32(c[0][nt], a[0][0], a[0][1], a[0][2], a[0][3], b0, b1);
                mma_tf32(c[1][nt], a[1][0], a[1][1], a[1][2], a[1][3], b0, b1);
            }
        }
    }
    __syncthreads();
    #pragma unroll
    for (int mf = 0; mf < 2; mf++) {
        int rb = mrow0 + mf * 16;
        #pragma unroll
        for (int nt = 0; nt < 8; nt++) {
            int col0 = ncol0 + nt * 8 + 2 * tig;
            float bb0 = fc1b[col0], bb1 = fc1b[col0 + 1];
            Hs[(rb + gid) * HS_LD + col0]     = fmaxf(c[mf][nt][0] + bb0, 0.f);
            Hs[(rb + gid) * HS_LD + col0 + 1] = fmaxf(c[mf][nt][1] + bb1, 0.f);
            Hs[(rb + gid + 8) * HS_LD + col0]     = fmaxf(c[mf][nt][2] + bb0, 0.f);
            Hs[(rb + gid + 8) * HS_LD + col0 + 1] = fmaxf(c[mf][nt][3] + bb1, 0.f);
        }
    }
    __syncthreads();
    #pragma unroll
    for (int pp = 0; pp < 2; pp++) {
        int p = tid + pp * 512;
        int r = p >> 3, o = p & 7;
        size_t row = n0 + r;
        float a = fc2b[o];
        const float4* h4 = (const float4*)(Hs + r * HS_LD);
        const float4* w4 = (const float4*)(s_fc2 + o * 256);
        #pragma unroll 8
        for (int jj = 0; jj < 64; jj++) {
            float4 h = h4[jj], w = w4[jj];
            a += h.x * w.x + h.y * w.y + h.z * w.z + h.w * w.w;
        }
        if (row < NCELL) nodes_out[row * OUTD + o] = fmaxf(a, 0.f);
    }
    if (tid < 128) {
        size_t row = n0 + tid;
        if (row < NCELL) {
            float s = outb[0] + rpart4[tid][0] + rpart4[tid][1] + rpart4[tid][2] + rpart4[tid][3];
            ret_out[row] = s;
        }
    }
}

// ---------------- launch ----------------
static inline int cdiv(long long a, long long b) { return (int)((a + b - 1) / b); }

extern "C" void kernel_launch(void* const* d_in, const int* in_sizes, int n_in,
                              void* d_out, int out_size) {
    const float* node_f     = (const float*)d_in[0];
    const float* net_f      = (const float*)d_in[1];
    const int*   sink_node  = (const int*)d_in[2];
    const int*   sink_net   = (const int*)d_in[3];
    const int*   src_node   = (const int*)d_in[4];
    const int*   src_net    = (const int*)d_in[5];
    const int*   batch      = (const int*)d_in[6];
    const float* w_node     = (const float*)d_in[8];
    const float* b_node     = (const float*)d_in[9];
    const float* w_net      = (const float*)d_in[10];
    const float* b_net      = (const float*)d_in[11];
    const float* vn_emb     = (const float*)d_in[12];
    const float* vn_mlp_w   = (const float*)d_in[13];
    const float* vn_mlp_b   = (const float*)d_in[14];
    const float* conv_net_w = (const float*)d_in[15];
    const float* conv_net_b = (const float*)d_in[16];
    const float* conv_node_w= (const float*)d_in[17];
    const float* conv_node_b= (const float*)d_in[18];
    const float* fc1_w      = (const float*)d_in[19];
    const float* fc1_b      = (const float*)d_in[20];
    const float* fc2_w      = (const float*)d_in[21];
    const float* fc2_b      = (const float*)d_in[22];
    const float* out_w      = (const float*)d_in[23];
    const float* out_b      = (const float*)d_in[24];

    static bool attr_done = false;
    if (!attr_done) {
        cudaFuncSetAttribute(k_head_mma, cudaFuncAttributeMaxDynamicSharedMemorySize, DSMEM_HEAD);
        cudaFuncSetAttribute(k_net_mma, cudaFuncAttributeMaxDynamicSharedMemorySize, DSMEM_NET);
        cudaFuncSetAttribute(k_node_mma, cudaFuncAttributeMaxDynamicSharedMemorySize, DSMEM_NODE);
        attr_done = true;
    }

    float *p_cat, *p_net;
    __half *p_cath;
    cudaGetSymbolAddress((void**)&p_cat, g_cat);
    cudaGetSymbolAddress((void**)&p_net, g_net);
    cudaGetSymbolAddress((void**)&p_cath, g_cath);

    // setup
    k_zero_all<<<cdiv(NCELL, 256), 256>>>();
    k_count<<<cdiv(EKE, 256), 256>>>(sink_node, sink_net, src_net);
    k_prep<<<cdiv(NCELL, 256), 256>>>(batch, vn_emb);
    k_embed<<<EMB_GRID, 256>>>(node_f, w_node, b_node, p_cat, NCELL, CATD, 1, batch, p_cath);
    k_embed<<<EMB_GRID, 256>>>(net_f, w_net, b_net, p_net, MNET, EMB, 0, nullptr, nullptr);
    {
        int nb = cdiv(SCAN_TOT, 1024);
        k_scan1<<<nb, 256>>>();
        k_scan2<<<1, 1024>>>(nb);
        k_scan3<<<nb, 256>>>();
    }
    k_scat<<<cdiv(EKE, 256), 256>>>(sink_node, sink_net, src_node, src_net, batch);

    // layers
    for (int l = 0; l < NL; l++) {
        k_net_mma<<<CONV_GRID, 256, DSMEM_NET>>>(conv_net_w + l * 4096, conv_net_b + l * 64, l);
        k_node_mma<<<CONV_GRID, 256, DSMEM_NODE>>>(conv_node_w + l * 4096, conv_node_b + l * 64, batch, l);
        if (l < NL - 1) {
            k_vn<<<VN, EMB>>>(vn_mlp_w + l * 4096, vn_mlp_b + l * 64);
            if (l + 1 < NL - 1)
                k_pool_cat<<<512, 256>>>(batch, l + 1);
        }
    }

    // head
    float* nodes_out = (float*)d_out;
    float* ret_out = (float*)d_out + (size_t)NCELL * OUTD;
    k_head_mma<<<cdiv(NCELL, 128), 512, DSMEM_HEAD>>>(fc1_w, fc1_b, fc2_w, fc2_b,
                                                      out_w, out_b, p_cat, nodes_out, ret_out);
}

// round 14
// speedup vs baseline: 1.0677x; 1.0677x over previous
#include <cuda_runtime.h>
#include <cuda_fp16.h>
#include <cstdint>

#define NCELL 500000
#define MNET  450000
#define EKE   2000000
#define ESE   500000
#define ECOMB (EKE + ESE)
#define EMB   64
#define VN    64
#define NL    3
#define CATD  256
#define OUTD  8
#define NODE_MASK 0x7FFFF
#define SCAN_TOT (MNET + NCELL)

// ---------------- scratch ----------------
__device__ int   g_cnt_n[NCELL];
__device__ int   g_cnt_e[MNET];
__device__ int   g_cnt_comb[MNET];
__device__ int   g_off_net[MNET + 1];
__device__ int   g_cur_net[MNET];
__device__ int   g_off_node[NCELL + 1];
__device__ int   g_cur_node[NCELL];
__device__ int2  g_csr_net[ECOMB];     // (node | batch<<19, weight bits)
__device__ int2  g_csr_node[EKE];      // (net, weight bits)
__device__ int   g_partial[1024];
__device__ float g_rsq_n[NCELL];
__device__ float g_rsq_e[MNET];
__device__ float g_cat[(size_t)NCELL * CATD];
__device__ float g_net[(size_t)MNET * EMB];
__device__ __half g_cath[(size_t)NCELL * EMB];   // fp16 mirror of current cat layer slice
__device__ __half g_neth[(size_t)MNET * EMB];    // fp16 mirror of h_net
__device__ float g_vn[VN * EMB];
__device__ float g_poolA[VN * EMB];   // pool(0): embed -> vn0.  invariant: zero at entry
__device__ float g_poolB[VN * EMB];   // pool(1): node_mma(0) -> vn1.  invariant: zero at entry
__device__ float g_cntvn[VN];

// ---------------- helpers ----------------
__device__ __forceinline__ uint32_t f2tf32(float v) {
    uint32_t r; asm("cvt.rna.tf32.f32 %0, %1;" : "=r"(r) : "f"(v)); return r;
}
__device__ __forceinline__ void split_tf32(float v, uint32_t& hi, uint32_t& lo) {
    hi = f2tf32(v);
    lo = f2tf32(v - __uint_as_float(hi));
}
__device__ __forceinline__ void mma_tf32(float* c, uint32_t a0, uint32_t a1, uint32_t a2,
                                         uint32_t a3, uint32_t b0, uint32_t b1) {
    asm("mma.sync.aligned.m16n8k8.row.col.f32.tf32.tf32.f32 "
        "{%0,%1,%2,%3},{%4,%5,%6,%7},{%8,%9},{%0,%1,%2,%3};"
        : "+f"(c[0]), "+f"(c[1]), "+f"(c[2]), "+f"(c[3])
        : "r"(a0), "r"(a1), "r"(a2), "r"(a3), "r"(b0), "r"(b1));
}

// ---------------- setup ----------------
__global__ void k_zero_all() {
    int i = blockIdx.x * blockDim.x + threadIdx.x;
    if (i < NCELL) g_cnt_n[i] = 0;
    if (i < MNET) { g_cnt_e[i] = 0; g_cnt_comb[i] = 0; }
    if (i < VN) g_cntvn[i] = 0.f;
}
__global__ void k_count(const int* __restrict__ sn, const int* __restrict__ se,
                        const int* __restrict__ src_net) {
    int i = blockIdx.x * blockDim.x + threadIdx.x;
    if (i < EKE) { atomicAdd(&g_cnt_n[sn[i]], 1); atomicAdd(&g_cnt_e[se[i]], 1); }
    if (i < ESE) atomicAdd(&g_cnt_comb[src_net[i]], 1);
}
__global__ void k_prep(const int* __restrict__ batch, const float* __restrict__ vn_emb) {
    __shared__ float hist[VN];
    int tid = threadIdx.x;
    int i = blockIdx.x * blockDim.x + tid;
    if (tid < VN) hist[tid] = 0.f;
    __syncthreads();
    if (i < MNET) {
        int ce = g_cnt_e[i];
        g_cnt_comb[i] += ce;
        g_rsq_e[i] = rsqrtf(fmaxf((float)ce, 1.f));
    }
    if (i < NCELL) {
        g_rsq_n[i] = rsqrtf(fmaxf((float)g_cnt_n[i], 1.f));
        atomicAdd(&hist[batch[i]], 1.f);
    }
    if (i < VN * EMB) g_vn[i] = vn_emb[i & 63];
    __syncthreads();
    if (tid < VN) atomicAdd(&g_cntvn[tid], hist[tid]);
}

// ---------------- combined exclusive scan over [cnt_comb | cnt_n] ----------------
__device__ __forceinline__ int comb_cnt(int i) {
    return (i < MNET) ? g_cnt_comb[i] : g_cnt_n[i - MNET];
}
__global__ void k_scan1() {
    __shared__ int s[256];
    int base = blockIdx.x * 1024, t = threadIdx.x;
    int sum = 0;
    #pragma unroll
    for (int q = 0; q < 4; q++) { int i = base + q * 256 + t; sum += (i < SCAN_TOT) ? comb_cnt(i) : 0; }
    s[t] = sum; __syncthreads();
    for (int st = 128; st > 0; st >>= 1) {
        if (t < st) s[t] += s[t + st];
        __syncthreads();
    }
    if (t == 0) g_partial[blockIdx.x] = s[0];
}
__global__ void k_scan2(int nb) {
    __shared__ int s[1024];
    int t = threadIdx.x;
    int v = (t < nb) ? g_partial[t] : 0;
    s[t] = v; __syncthreads();
    for (int st = 1; st < 1024; st <<= 1) {
        int a = (t >= st) ? s[t - st] : 0;
        __syncthreads();
        s[t] += a; __syncthreads();
    }
    if (t < nb) g_partial[t] = s[t] - v;
}
__global__ void k_scan3() {
    __shared__ int s[256];
    int t = threadIdx.x, base = blockIdx.x * 1024;
    int v[4], sum = 0;
    #pragma unroll
    for (int q = 0; q < 4; q++) { int i = base + t * 4 + q; v[q] = (i < SCAN_TOT) ? comb_cnt(i) : 0; sum += v[q]; }
    s[t] = sum; __syncthreads();
    int mine = sum;
    for (int st = 1; st < 256; st <<= 1) {
        int a = (t >= st) ? s[t - st] : 0;
        __syncthreads();
        s[t] += a; __syncthreads();
    }
    int ex = s[t] - mine + g_partial[blockIdx.x];
    #pragma unroll
    for (int q = 0; q < 4; q++) {
        int i = base + t * 4 + q;
        if (i < SCAN_TOT) {
            if (i < MNET) { g_off_net[i] = ex; g_cur_net[i] = ex; }
            else { g_off_node[i - MNET] = ex - ECOMB; g_cur_node[i - MNET] = ex - ECOMB; }
            ex += v[q];
        }
    }
    if (blockIdx.x == 0 && t == 0) {
        g_off_net[MNET] = ECOMB;
        g_off_node[NCELL] = EKE;
    }
}

// ---------------- combined CSR scatter ----------------
__global__ void k_scat(const int* __restrict__ sink_node, const int* __restrict__ sink_net,
                       const int* __restrict__ src_node, const int* __restrict__ src_net,
                       const int* __restrict__ batch) {
    int e = blockIdx.x * blockDim.x + threadIdx.x;
    if (e < EKE) {
        int node = sink_node[e], net = sink_net[e];
        float ew = g_rsq_n[node] * g_rsq_e[net];
        int packed = node | (batch[node] << 19);
        int pn = atomicAdd(&g_cur_net[net], 1);
        g_csr_net[pn] = make_int2(packed, __float_as_int(ew));
        int pd = atomicAdd(&g_cur_node[node], 1);
        g_csr_node[pd] = make_int2(net, __float_as_int(ew));
    }
    if (e < ESE) {
        int node = src_node[e];
        int packed = node | (batch[node] << 19);
        int pos = atomicAdd(&g_cur_net[src_net[e]], 1);
        g_csr_net[pos] = make_int2(packed, __float_as_int(1.f));
    }
}

// ---------------- persistent embedding (+ optional fused VN pooling, fp16 mirror) ----------------
#define EMB_GRID 592
__global__ __launch_bounds__(256) void k_embed(
    const float* __restrict__ feat, const float* __restrict__ w, const float* __restrict__ b,
    float* __restrict__ out, int nrows, int ostride,
    int doPool, const int* __restrict__ batch, __half* __restrict__ mirror) {
    __shared__ float s_w[16 * EMB];
    __shared__ float s_in[32][17];
    __shared__ int   s_batch[32];
    __shared__ float s_pool[VN * EMB];
    int tid = threadIdx.x;
    int j = tid & 63, rq = tid >> 6;

    for (int i = tid; i < 16 * EMB; i += 256) s_w[i] = w[i];
    if (doPool) for (int i = tid; i < VN * EMB; i += 256) s_pool[i] = 0.f;
    float breg = b[j];
    __syncthreads();
    float wreg[16];
    #pragma unroll
    for (int k = 0; k < 16; k++) wreg[k] = s_w[k * EMB + j];

    int ntiles = (nrows + 31) / 32;
    for (int tile = blockIdx.x; tile < ntiles; tile += gridDim.x) {
        int base = tile * 32;
        __syncthreads();
        if (tid < 128) {
            int r = tid >> 2, k4 = tid & 3;
            int row = base + r;
            float4 v = (row < nrows) ? ((const float4*)feat)[(size_t)row * 4 + k4]
                                     : make_float4(0.f, 0.f, 0.f, 0.f);
            s_in[r][k4 * 4 + 0] = v.x; s_in[r][k4 * 4 + 1] = v.y;
            s_in[r][k4 * 4 + 2] = v.z; s_in[r][k4 * 4 + 3] = v.w;
        }
        if (doPool && tid < 32) {
            int row = base + tid;
            s_batch[tid] = (row < nrows) ? batch[row] : 0;
        }
        __syncthreads();
        #pragma unroll
        for (int s = 0; s < 8; s++) {
            int r = rq + s * 4;
            int row = base + r;
            if (row < nrows) {
                float a = breg;
                #pragma unroll
                for (int k = 0; k < 16; k++) a += s_in[r][k] * wreg[k];
                a = fmaxf(a, 0.f);
                out[(size_t)row * ostride + j] = a;
                if (mirror) mirror[(size_t)row * EMB + j] = __float2half_rn(a);
                if (doPool) atomicAdd(&s_pool[s_batch[r] * EMB + j], a);
            }
        }
    }
    if (doPool) {
        __syncthreads();
        for (int i = tid; i < VN * EMB; i += 256) atomicAdd(&g_poolA[i], s_pool[i]);
    }
}

// ---------------- VN update (consumes + re-zeros given pool buffer) ----------------
__global__ void k_vn(const float* __restrict__ w, const float* __restrict__ b,
                     float* __restrict__ pool) {
    int v = blockIdx.x, j = threadIdx.x;
    __shared__ float t[EMB];
    float cnt = g_cntvn[v];
    float vv = g_vn[v * EMB + j];
    t[j] = (pool[v * EMB + j] + cnt * vv) / fmaxf(cnt, 1.f) + vv;
    pool[v * EMB + j] = 0.f;
    __syncthreads();
    float acc = b[j];
    #pragma unroll
    for (int k = 0; k < EMB; k++) acc += t[k] * w[k * EMB + j];
    g_vn[v * EMB + j] = vv + fmaxf(acc, 0.f);
}

// =====================================================================
// Persistent fused gather + 3xTF32 mma conv kernels (R11 config + offset prefetch)
// =====================================================================
#define CLD 68
#define DSMEM_NET  ((64 * CLD + 64 * CLD + VN * EMB + EMB) * 4)               // ~51 KB
#define DSMEM_NODE ((64 * CLD + 64 * CLD + EMB) * 4 + VN * EMB * 4)           // ~51.5 KB
#define CONV_GRID 592
#define NTILES_NET  ((MNET + 63) / 64)
#define NTILES_NODE ((NCELL + 63) / 64)

__device__ __forceinline__ void conv_mma_epilogue(
    float* As, float* Ws, const float* sb,
    int tid, long long row0, int nrows, float* __restrict__ outbuf,
    int ostride4, int ooff4, __half* __restrict__ mirror,
    float* s_pool, const int* __restrict__ batch)
{
    int warp = tid >> 5, lane = tid & 31;
    int gid = lane >> 2, tig = lane & 3;
    int mrow0 = (warp >> 1) * 16;
    int ncol0 = (warp & 1) * 32;

    float c[4][4];
    #pragma unroll
    for (int nt = 0; nt < 4; nt++)
        #pragma unroll
        for (int q = 0; q < 4; q++) c[nt][q] = 0.f;

    #pragma unroll
    for (int kk = 0; kk < 8; kk++) {
        int kb = kk * 8;
        uint32_t ah0, al0, ah1, al1, ah2, al2, ah3, al3;
        split_tf32(As[(mrow0 + gid) * CLD + kb + tig], ah0, al0);
        split_tf32(As[(mrow0 + gid + 8) * CLD + kb + tig], ah1, al1);
        split_tf32(As[(mrow0 + gid) * CLD + kb + tig + 4], ah2, al2);
        split_tf32(As[(mrow0 + gid + 8) * CLD + kb + tig + 4], ah3, al3);
        #pragma unroll
        for (int nt = 0; nt < 4; nt++) {
            int col = ncol0 + nt * 8 + gid;
            uint32_t bh0, bl0, bh1, bl1;
            split_tf32(Ws[(kb + tig) * CLD + col], bh0, bl0);
            split_tf32(Ws[(kb + tig + 4) * CLD + col], bh1, bl1);
            mma_tf32(c[nt], ah0, ah1, ah2, ah3, bh0, bh1);
            mma_tf32(c[nt], ah0, ah1, ah2, ah3, bl0, bl1);
            mma_tf32(c[nt], al0, al1, al2, al3, bh0, bh1);
        }
    }
    __syncthreads();
    #pragma unroll
    for (int nt = 0; nt < 4; nt++) {
        int col0 = ncol0 + nt * 8 + 2 * tig;
        float b0 = sb[col0], b1 = sb[col0 + 1];
        As[(mrow0 + gid) * CLD + col0]     = fmaxf(c[nt][0] + b0, 0.f);
        As[(mrow0 + gid) * CLD + col0 + 1] = fmaxf(c[nt][1] + b1, 0.f);
        As[(mrow0 + gid + 8) * CLD + col0]     = fmaxf(c[nt][2] + b0, 0.f);
        As[(mrow0 + gid + 8) * CLD + col0 + 1] = fmaxf(c[nt][3] + b1, 0.f);
    }
    __syncthreads();
    #pragma unroll
    for (int q = 0; q < 4; q++) {
        int idx = q * 256 + tid;
        int r = idx >> 4, c4 = idx & 15;
        long long row = row0 + r;
        if (row < nrows) {
            float4 v = *(const float4*)(As + r * CLD + c4 * 4);
            ((float4*)outbuf)[row * ostride4 + ooff4 + c4] = v;
            union { __half2 h[2]; uint2 u; } pk;
            pk.h[0] = __floats2half2_rn(v.x, v.y);
            pk.h[1] = __floats2half2_rn(v.z, v.w);
            ((uint2*)mirror)[row * 16 + c4] = pk.u;
            if (s_pool) {
                int bb = batch[row];
                float* dst = s_pool + bb * EMB + c4 * 4;
                atomicAdd(dst + 0, v.x);
                atomicAdd(dst + 1, v.y);
                atomicAdd(dst + 2, v.z);
                atomicAdd(dst + 3, v.w);
            }
        }
    }
}

__global__ __launch_bounds__(256) void k_net_mma(
    const float* __restrict__ W, const float* __restrict__ b, int l) {
    extern __shared__ float sm[];
    float* As = sm;
    float* Ws = sm + 64 * CLD;
    float* vns = sm + 128 * CLD;
    float* sb = vns + VN * EMB;
    int tid = threadIdx.x;
    for (int i = tid; i < EMB * EMB; i += 256) Ws[(i >> 6) * CLD + (i & 63)] = W[i];
    for (int i = tid; i < VN * EMB; i += 256) vns[i] = g_vn[i];
    if (tid < EMB) sb[tid] = b[tid];

    int warp = tid >> 5, lane = tid & 31;
    const __half2* cath2 = (const __half2*)g_cath;
    const float2* net2 = (const float2*)g_net;
    const float2* vn2 = (const float2*)vns;

    for (int tile = blockIdx.x; tile < NTILES_NET; tile += gridDim.x) {
        long long row0 = (long long)tile * 64;
        __syncthreads();
        // prefetch the 9 CSR offsets for this warp's 8 rows
        int offl = 0;
        {
            long long idx = row0 + warp * 8 + lane;
            if (lane < 9) offl = g_off_net[(idx > MNET) ? MNET : idx];
        }
        for (int q = 0; q < 8; q++) {
            int r = warp * 8 + q;
            long long netid = row0 + r;
            int p0 = __shfl_sync(0xffffffffu, offl, q);
            int p1 = __shfl_sync(0xffffffffu, offl, q + 1);
            float2 acc = make_float2(0.f, 0.f);
            if (netid < MNET) {
                acc = net2[netid * 32 + lane];
                int p = p0;
                for (; p + 3 < p1; p += 4) {
                    int2 e0 = g_csr_net[p], e1 = g_csr_net[p + 1];
                    int2 e2 = g_csr_net[p + 2], e3 = g_csr_net[p + 3];
                    int n0 = e0.x & NODE_MASK, b0 = e0.x >> 19;
                    int n1 = e1.x & NODE_MASK, b1 = e1.x >> 19;
                    int n2 = e2.x & NODE_MASK, b2 = e2.x >> 19;
                    int n3 = e3.x & NODE_MASK, b3 = e3.x >> 19;
                    float2 v0 = __half22float2(cath2[(size_t)n0 * 32 + lane]);
                    float2 v1 = __half22float2(cath2[(size_t)n1 * 32 + lane]);
                    float2 v2 = __half22float2(cath2[(size_t)n2 * 32 + lane]);
                    float2 v3 = __half22float2(cath2[(size_t)n3 * 32 + lane]);
                    float2 u0 = vn2[b0 * 32 + lane];
                    float2 u1 = vn2[b1 * 32 + lane];
                    float2 u2 = vn2[b2 * 32 + lane];
                    float2 u3 = vn2[b3 * 32 + lane];
                    float w0 = __int_as_float(e0.y), w1 = __int_as_float(e1.y);
                    float w2 = __int_as_float(e2.y), w3 = __int_as_float(e3.y);
                    acc.x += w0 * (v0.x + u0.x) + w1 * (v1.x + u1.x)
                           + w2 * (v2.x + u2.x) + w3 * (v3.x + u3.x);
                    acc.y += w0 * (v0.y + u0.y) + w1 * (v1.y + u1.y)
                           + w2 * (v2.y + u2.y) + w3 * (v3.y + u3.y);
                }
                for (; p < p1; p++) {
                    int2 e0 = g_csr_net[p];
                    int n0 = e0.x & NODE_MASK, b0 = e0.x >> 19;
                    float2 v0 = __half22float2(cath2[(size_t)n0 * 32 + lane]);
                    float2 u0 = vn2[b0 * 32 + lane];
                    float w0 = __int_as_float(e0.y);
                    acc.x += w0 * (v0.x + u0.x);
                    acc.y += w0 * (v0.y + u0.y);
                }
            }
            *(float2*)(As + r * CLD + 2 * lane) = acc;
        }
        __syncthreads();
        conv_mma_epilogue(As, Ws, sb, tid, row0, MNET, (float*)g_net, 16, 0, g_neth,
                          nullptr, nullptr);
    }
}

__global__ __launch_bounds__(256) void k_node_mma(
    const float* __restrict__ W, const float* __restrict__ b,
    const int* __restrict__ batch, int l, int doPool) {
    extern __shared__ float sm[];
    float* As = sm;
    float* Ws = sm + 64 * CLD;
    float* sb = sm + 128 * CLD;
    float* s_pool = sm + 128 * CLD + EMB;
    int tid = threadIdx.x;
    for (int i = tid; i < EMB * EMB; i += 256) Ws[(i >> 6) * CLD + (i & 63)] = W[i];
    if (tid < EMB) sb[tid] = b[tid];
    if (doPool) for (int i = tid; i < VN * EMB; i += 256) s_pool[i] = 0.f;

    int warp = tid >> 5, lane = tid & 31;
    const float2* cat2 = (const float2*)g_cat;
    const __half2* neth2 = (const __half2*)g_neth;
    const float2* vn2 = (const float2*)g_vn;
    float* poolArg = doPool ? s_pool : nullptr;

    for (int tile = blockIdx.x; tile < NTILES_NODE; tile += gridDim.x) {
        long long row0 = (long long)tile * 64;
        __syncthreads();
        int offl = 0;
        {
            long long idx = row0 + warp * 8 + lane;
            if (lane < 9) offl = g_off_node[(idx > NCELL) ? NCELL : idx];
        }
        for (int q = 0; q < 8; q++) {
            int r = warp * 8 + q;
            long long node = row0 + r;
            int p0 = __shfl_sync(0xffffffffu, offl, q);
            int p1 = __shfl_sync(0xffffffffu, offl, q + 1);
            float2 acc = make_float2(0.f, 0.f);
            if (node < NCELL) {
                int bb = batch[node];
                float2 v = cat2[node * 128 + l * 32 + lane];
                float2 u = vn2[bb * 32 + lane];
                acc.x = v.x + u.x; acc.y = v.y + u.y;
                int p = p0;
                for (; p + 3 < p1; p += 4) {
                    int2 e0 = g_csr_node[p], e1 = g_csr_node[p + 1];
                    int2 e2 = g_csr_node[p + 2], e3 = g_csr_node[p + 3];
                    float2 v0 = __half22float2(neth2[(size_t)e0.x * 32 + lane]);
                    float2 v1 = __half22float2(neth2[(size_t)e1.x * 32 + lane]);
                    float2 v2 = __half22float2(neth2[(size_t)e2.x * 32 + lane]);
                    float2 v3 = __half22float2(neth2[(size_t)e3.x * 32 + lane]);
                    float w0 = __int_as_float(e0.y), w1 = __int_as_float(e1.y);
                    float w2 = __int_as_float(e2.y), w3 = __int_as_float(e3.y);
                    acc.x += w0 * v0.x + w1 * v1.x + w2 * v2.x + w3 * v3.x;
                    acc.y += w0 * v0.y + w1 * v1.y + w2 * v2.y + w3 * v3.y;
                }
                for (; p < p1; p++) {
                    int2 e0 = g_csr_node[p];
                    float2 v0 = __half22float2(neth2[(size_t)e0.x * 32 + lane]);
                    float w0 = __int_as_float(e0.y);
                    acc.x += w0 * v0.x; acc.y += w0 * v0.y;
                }
            }
            *(float2*)(As + r * CLD + 2 * lane) = acc;
        }
        __syncthreads();
        conv_mma_epilogue(As, Ws, sb, tid, row0, NCELL, (float*)g_cat, 64, (l + 1) * 16, g_cath,
                          poolArg, batch);
    }
    if (doPool) {
        __syncthreads();
        for (int i = tid; i < VN * EMB; i += 256) atomicAdd(&g_poolB[i], s_pool[i]);
    }
}

// ---------------- head: 128 rows x 256 cols, 512 threads ----------------
#define AS_LD 68
#define BS_LD 260
#define HS_LD 260
#define DSMEM_HEAD (128 * HS_LD * 4)

__global__ __launch_bounds__(512) void k_head_mma(
    const float* __restrict__ fc1w, const float* __restrict__ fc1b,
    const float* __restrict__ fc2w, const float* __restrict__ fc2b,
    const float* __restrict__ outw, const float* __restrict__ outb,
    const float* __restrict__ cat,
    float* __restrict__ nodes_out, float* __restrict__ ret_out) {
    extern __shared__ float sm[];
    float* As = sm;
    float* Bs = sm + 128 * AS_LD;
    float* Hs = sm;
    __shared__ float s_ow[CATD];
    __shared__ float s_fc2[8 * 256];
    __shared__ float rpart4[128][4];

    int tid = threadIdx.x;
    int warp = tid >> 5, lane = tid & 31;
    int gid = lane >> 2, tig = lane & 3;
    int mrow0 = (warp >> 2) * 32;
    int ncol0 = (warp & 3) * 64;
    size_t n0 = (size_t)blockIdx.x * 128;

    if (tid < CATD) s_ow[tid] = outw[tid];
    for (int i = tid; i < 2048; i += 512) {
        int o = i >> 8, jj = i & 255;
        s_fc2[o * 256 + jj] = fc2w[jj * 8 + o];
    }
    { int r = tid >> 2, q = tid & 3; rpart4[r][q] = 0.f; }

    float c[2][8][4];
    #pragma unroll
    for (int mf = 0; mf < 2; mf++)
        #pragma unroll
        for (int nt = 0; nt < 8; nt++)
            #pragma unroll
            for (int q = 0; q < 4; q++) c[mf][nt][q] = 0.f;

    for (int kc = 0; kc < 4; kc++) {
        __syncthreads();
        #pragma unroll
        for (int q = 0; q < 4; q++) {
            int idx = q * 512 + tid;
            int r = idx >> 4, k4 = idx & 15;
            size_t row = n0 + r;
            float4 v = (row < NCELL)
                ? *(const float4*)(cat + row * CATD + kc * 64 + k4 * 4)
                : make_float4(0.f, 0.f, 0.f, 0.f);
            *(float4*)(As + r * AS_LD + k4 * 4) = v;
        }
        #pragma unroll
        for (int q = 0; q < 8; q++) {
            int idx = q * 512 + tid;
            int r = idx >> 6, j4 = idx & 63;
            float4 v = *(const float4*)(fc1w + (size_t)(kc * 64 + r) * 256 + j4 * 4);
            *(float4*)(Bs + r * BS_LD + j4 * 4) = v;
        }
        __syncthreads();
        {
            int r = tid >> 2, q = tid & 3;
            float a = 0.f;
            #pragma unroll
            for (int kk = 0; kk < 16; kk++)
                a += As[r * AS_LD + q * 16 + kk] * s_ow[kc * 64 + q * 16 + kk];
            rpart4[r][q] += a;
        }
        #pragma unroll
        for (int kk = 0; kk < 8; kk++) {
            int kb = kk * 8;
            uint32_t a[2][4];
            #pragma unroll
            for (int mf = 0; mf < 2; mf++) {
                int rb = mrow0 + mf * 16;
                a[mf][0] = f2tf32(As[(rb + gid) * AS_LD + kb + tig]);
                a[mf][1] = f2tf32(As[(rb + gid + 8) * AS_LD + kb + tig]);
                a[mf][2] = f2tf32(As[(rb + gid) * AS_LD + kb + tig + 4]);
                a[mf][3] = f2tf32(As[(rb + gid + 8) * AS_LD + kb + tig + 4]);
            }
            #pragma unroll
            for (int nt = 0; nt < 8; nt++) {
                int col = ncol0 + nt * 8 + gid;
                uint32_t b0 = f2tf32(Bs[(kb + tig) * BS_LD + col]);
                uint32_t b1 = f2tf32(Bs[(kb + tig + 4) * BS_LD + col]);
                mma_tf32(c[0][nt], a[0][0], a[0][1], a[0][2], a[0][3], b0, b1);
                mma_tf32(c[1][nt], a[1][0], a[1][1], a[1][2], a[1][3], b0, b1);
            }
        }
    }
    __syncthreads();
    #pragma unroll
    for (int mf = 0; mf < 2; mf++) {
        int rb = mrow0 + mf * 16;
        #pragma unroll
        for (int nt = 0; nt < 8; nt++) {
            int col0 = ncol0 + nt * 8 + 2 * tig;
            float bb0 = fc1b[col0], bb1 = fc1b[col0 + 1];
            Hs[(rb + gid) * HS_LD + col0]     = fmaxf(c[mf][nt][0] + bb0, 0.f);
            Hs[(rb + gid) * HS_LD + col0 + 1] = fmaxf(c[mf][nt][1] + bb1, 0.f);
            Hs[(rb + gid + 8) * HS_LD + col0]     = fmaxf(c[mf][nt][2] + bb0, 0.f);
            Hs[(rb + gid + 8) * HS_LD + col0 + 1] = fmaxf(c[mf][nt][3] + bb1, 0.f);
        }
    }
    __syncthreads();
    #pragma unroll
    for (int pp = 0; pp < 2; pp++) {
        int p = tid + pp * 512;
        int r = p >> 3, o = p & 7;
        size_t row = n0 + r;
        float a = fc2b[o];
        const float4* h4 = (const float4*)(Hs + r * HS_LD);
        const float4* w4 = (const float4*)(s_fc2 + o * 256);
        #pragma unroll 8
        for (int jj = 0; jj < 64; jj++) {
            float4 h = h4[jj], w = w4[jj];
            a += h.x * w.x + h.y * w.y + h.z * w.z + h.w * w.w;
        }
        if (row < NCELL) nodes_out[row * OUTD + o] = fmaxf(a, 0.f);
    }
    if (tid < 128) {
        size_t row = n0 + tid;
        if (row < NCELL) {
            float s = outb[0] + rpart4[tid][0] + rpart4[tid][1] + rpart4[tid][2] + rpart4[tid][3];
            ret_out[row] = s;
        }
    }
}

// ---------------- launch ----------------
static inline int cdiv(long long a, long long b) { return (int)((a + b - 1) / b); }

extern "C" void kernel_launch(void* const* d_in, const int* in_sizes, int n_in,
                              void* d_out, int out_size) {
    const float* node_f     = (const float*)d_in[0];
    const float* net_f      = (const float*)d_in[1];
    const int*   sink_node  = (const int*)d_in[2];
    const int*   sink_net   = (const int*)d_in[3];
    const int*   src_node   = (const int*)d_in[4];
    const int*   src_net    = (const int*)d_in[5];
    const int*   batch      = (const int*)d_in[6];
    const float* w_node     = (const float*)d_in[8];
    const float* b_node     = (const float*)d_in[9];
    const float* w_net      = (const float*)d_in[10];
    const float* b_net      = (const float*)d_in[11];
    const float* vn_emb     = (const float*)d_in[12];
    const float* vn_mlp_w   = (const float*)d_in[13];
    const float* vn_mlp_b   = (const float*)d_in[14];
    const float* conv_net_w = (const float*)d_in[15];
    const float* conv_net_b = (const float*)d_in[16];
    const float* conv_node_w= (const float*)d_in[17];
    const float* conv_node_b= (const float*)d_in[18];
    const float* fc1_w      = (const float*)d_in[19];
    const float* fc1_b      = (const float*)d_in[20];
    const float* fc2_w      = (const float*)d_in[21];
    const float* fc2_b      = (const float*)d_in[22];
    const float* out_w      = (const float*)d_in[23];
    const float* out_b      = (const float*)d_in[24];

    static bool attr_done = false;
    if (!attr_done) {
        cudaFuncSetAttribute(k_head_mma, cudaFuncAttributeMaxDynamicSharedMemorySize, DSMEM_HEAD);
        cudaFuncSetAttribute(k_net_mma, cudaFuncAttributeMaxDynamicSharedMemorySize, DSMEM_NET);
        cudaFuncSetAttribute(k_node_mma, cudaFuncAttributeMaxDynamicSharedMemorySize, DSMEM_NODE);
        attr_done = true;
    }

    float *p_cat, *p_net, *p_poolA, *p_poolB;
    __half *p_cath;
    cudaGetSymbolAddress((void**)&p_cat, g_cat);
    cudaGetSymbolAddress((void**)&p_net, g_net);
    cudaGetSymbolAddress((void**)&p_cath, g_cath);
    cudaGetSymbolAddress((void**)&p_poolA, g_poolA);
    cudaGetSymbolAddress((void**)&p_poolB, g_poolB);

    // setup
    k_zero_all<<<cdiv(NCELL, 256), 256>>>();
    k_count<<<cdiv(EKE, 256), 256>>>(sink_node, sink_net, src_net);
    k_prep<<<cdiv(NCELL, 256), 256>>>(batch, vn_emb);
    k_embed<<<EMB_GRID, 256>>>(node_f, w_node, b_node, p_cat, NCELL, CATD, 1, batch, p_cath);
    k_embed<<<EMB_GRID, 256>>>(net_f, w_net, b_net, p_net, MNET, EMB, 0, nullptr, nullptr);
    {
        int nb = cdiv(SCAN_TOT, 1024);
        k_scan1<<<nb, 256>>>();
        k_scan2<<<1, 1024>>>(nb);
        k_scan3<<<nb, 256>>>();
    }
    k_scat<<<cdiv(EKE, 256), 256>>>(sink_node, sink_net, src_node, src_net, batch);

    // layers; pool(0) fused into node embed (->poolA), pool(1) fused into node_mma(0) (->poolB)
    for (int l = 0; l < NL; l++) {
        k_net_mma<<<CONV_GRID, 256, DSMEM_NET>>>(conv_net_w + l * 4096, conv_net_b + l * 64, l);
        k_node_mma<<<CONV_GRID, 256, DSMEM_NODE>>>(conv_node_w + l * 4096, conv_node_b + l * 64,
                                                   batch, l, (l == 0) ? 1 : 0);
        if (l < NL - 1)
            k_vn<<<VN, EMB>>>(vn_mlp_w + l * 4096, vn_mlp_b + l * 64,
                              (l == 0) ? p_poolA : p_poolB);
    }

    // head
    float* nodes_out = (float*)d_out;
    float* ret_out = (float*)d_out + (size_t)NCELL * OUTD;
    k_head_mma<<<cdiv(NCELL, 128), 512, DSMEM_HEAD>>>(fc1_w, fc1_b, fc2_w, fc2_b,
                                                      out_w, out_b, p_cat, nodes_out, ret_out);
}

// round 17
// speedup vs baseline: 1.0944x; 1.0250x over previous
#include <cuda_runtime.h>
#include <cuda_fp16.h>
#include <cstdint>

#define NCELL 500000
#define MNET  450000
#define EKE   2000000
#define ESE   500000
#define ECOMB (EKE + ESE)
#define EMB   64
#define VN    64
#define NL    3
#define CATD  256
#define OUTD  8
#define NODE_MASK 0x7FFFF
#define SCAN_TOT (MNET + NCELL)

// ---------------- scratch ----------------
__device__ int   g_cnt_n[NCELL];
__device__ int   g_cnt_e[MNET];
__device__ int   g_cnt_comb[MNET];
__device__ int   g_off_net[MNET + 1];
__device__ int   g_cur_net[MNET];
__device__ int   g_off_node[NCELL + 1];
__device__ int   g_cur_node[NCELL];
__device__ int2  g_csr_net[ECOMB];     // (node | batch<<19, weight bits)
__device__ int2  g_csr_node[EKE];      // (net, weight bits)
__device__ int   g_partial[1024];
__device__ float g_rsq_n[NCELL];
__device__ float g_rsq_e[MNET];
__device__ __half g_cat[(size_t)NCELL * CATD];   // fp16 node_list, [n][l*64+j]
__device__ float g_net[(size_t)MNET * EMB];      // fp32 net_list[l] (self term)
__device__ __half g_neth[(size_t)MNET * EMB];    // fp16 mirror of h_net
__device__ float g_vn[VN * EMB];
__device__ float g_poolA[VN * EMB];   // pool(0): embed -> vn0.  invariant: zero at entry
__device__ float g_poolB[VN * EMB];   // pool(1): node_mma(0) -> vn1.  invariant: zero at entry
__device__ float g_cntvn[VN];

// ---------------- helpers ----------------
__device__ __forceinline__ uint32_t f2tf32(float v) {
    uint32_t r; asm("cvt.rna.tf32.f32 %0, %1;" : "=r"(r) : "f"(v)); return r;
}
__device__ __forceinline__ void split_tf32(float v, uint32_t& hi, uint32_t& lo) {
    hi = f2tf32(v);
    lo = f2tf32(v - __uint_as_float(hi));
}
__device__ __forceinline__ void mma_tf32(float* c, uint32_t a0, uint32_t a1, uint32_t a2,
                                         uint32_t a3, uint32_t b0, uint32_t b1) {
    asm("mma.sync.aligned.m16n8k8.row.col.f32.tf32.tf32.f32 "
        "{%0,%1,%2,%3},{%4,%5,%6,%7},{%8,%9},{%0,%1,%2,%3};"
        : "+f"(c[0]), "+f"(c[1]), "+f"(c[2]), "+f"(c[3])
        : "r"(a0), "r"(a1), "r"(a2), "r"(a3), "r"(b0), "r"(b1));
}

// ---------------- setup ----------------
__global__ void k_zero_all() {
    int i = blockIdx.x * blockDim.x + threadIdx.x;
    if (i < NCELL) g_cnt_n[i] = 0;
    if (i < MNET) { g_cnt_e[i] = 0; g_cnt_comb[i] = 0; }
    if (i < VN) g_cntvn[i] = 0.f;
}
__global__ void k_count(const int* __restrict__ sn, const int* __restrict__ se,
                        const int* __restrict__ src_net) {
    int i = blockIdx.x * blockDim.x + threadIdx.x;
    if (i < EKE) { atomicAdd(&g_cnt_n[sn[i]], 1); atomicAdd(&g_cnt_e[se[i]], 1); }
    if (i < ESE) atomicAdd(&g_cnt_comb[src_net[i]], 1);
}
__global__ void k_prep(const int* __restrict__ batch, const float* __restrict__ vn_emb) {
    __shared__ float hist[VN];
    int tid = threadIdx.x;
    int i = blockIdx.x * blockDim.x + tid;
    if (tid < VN) hist[tid] = 0.f;
    __syncthreads();
    if (i < MNET) {
        int ce = g_cnt_e[i];
        g_cnt_comb[i] += ce;
        g_rsq_e[i] = rsqrtf(fmaxf((float)ce, 1.f));
    }
    if (i < NCELL) {
        g_rsq_n[i] = rsqrtf(fmaxf((float)g_cnt_n[i], 1.f));
        atomicAdd(&hist[batch[i]], 1.f);
    }
    if (i < VN * EMB) g_vn[i] = vn_emb[i & 63];
    __syncthreads();
    if (tid < VN) atomicAdd(&g_cntvn[tid], hist[tid]);
}

// ---------------- combined exclusive scan over [cnt_comb | cnt_n] ----------------
__device__ __forceinline__ int comb_cnt(int i) {
    return (i < MNET) ? g_cnt_comb[i] : g_cnt_n[i - MNET];
}
__global__ void k_scan1() {
    __shared__ int s[256];
    int base = blockIdx.x * 1024, t = threadIdx.x;
    int sum = 0;
    #pragma unroll
    for (int q = 0; q < 4; q++) { int i = base + q * 256 + t; sum += (i < SCAN_TOT) ? comb_cnt(i) : 0; }
    s[t] = sum; __syncthreads();
    for (int st = 128; st > 0; st >>= 1) {
        if (t < st) s[t] += s[t + st];
        __syncthreads();
    }
    if (t == 0) g_partial[blockIdx.x] = s[0];
}
__global__ void k_scan2(int nb) {
    __shared__ int s[1024];
    int t = threadIdx.x;
    int v = (t < nb) ? g_partial[t] : 0;
    s[t] = v; __syncthreads();
    for (int st = 1; st < 1024; st <<= 1) {
        int a = (t >= st) ? s[t - st] : 0;
        __syncthreads();
        s[t] += a; __syncthreads();
    }
    if (t < nb) g_partial[t] = s[t] - v;
}
__global__ void k_scan3() {
    __shared__ int s[256];
    int t = threadIdx.x, base = blockIdx.x * 1024;
    int v[4], sum = 0;
    #pragma unroll
    for (int q = 0; q < 4; q++) { int i = base + t * 4 + q; v[q] = (i < SCAN_TOT) ? comb_cnt(i) : 0; sum += v[q]; }
    s[t] = sum; __syncthreads();
    int mine = sum;
    for (int st = 1; st < 256; st <<= 1) {
        int a = (t >= st) ? s[t - st] : 0;
        __syncthreads();
        s[t] += a; __syncthreads();
    }
    int ex = s[t] - mine + g_partial[blockIdx.x];
    #pragma unroll
    for (int q = 0; q < 4; q++) {
        int i = base + t * 4 + q;
        if (i < SCAN_TOT) {
            if (i < MNET) { g_off_net[i] = ex; g_cur_net[i] = ex; }
            else { g_off_node[i - MNET] = ex - ECOMB; g_cur_node[i - MNET] = ex - ECOMB; }
            ex += v[q];
        }
    }
    if (blockIdx.x == 0 && t == 0) {
        g_off_net[MNET] = ECOMB;
        g_off_node[NCELL] = EKE;
    }
}

// ---------------- combined CSR scatter ----------------
__global__ void k_scat(const int* __restrict__ sink_node, const int* __restrict__ sink_net,
                       const int* __restrict__ src_node, const int* __restrict__ src_net,
                       const int* __restrict__ batch) {
    int e = blockIdx.x * blockDim.x + threadIdx.x;
    if (e < EKE) {
        int node = sink_node[e], net = sink_net[e];
        float ew = g_rsq_n[node] * g_rsq_e[net];
        int packed = node | (batch[node] << 19);
        int pn = atomicAdd(&g_cur_net[net], 1);
        g_csr_net[pn] = make_int2(packed, __float_as_int(ew));
        int pd = atomicAdd(&g_cur_node[node], 1);
        g_csr_node[pd] = make_int2(net, __float_as_int(ew));
    }
    if (e < ESE) {
        int node = src_node[e];
        int packed = node | (batch[node] << 19);
        int pos = atomicAdd(&g_cur_net[src_net[e]], 1);
        g_csr_net[pos] = make_int2(packed, __float_as_int(1.f));
    }
}

// ---------------- persistent embedding (+ optional fused VN pooling) ----------------
#define EMB_GRID 592
__global__ __launch_bounds__(256) void k_embed(
    const float* __restrict__ feat, const float* __restrict__ w, const float* __restrict__ b,
    float* __restrict__ out32, int os32, __half* __restrict__ out16, int os16,
    int nrows, int doPool, const int* __restrict__ batch) {
    __shared__ float s_w[16 * EMB];
    __shared__ float s_in[32][17];
    __shared__ int   s_batch[32];
    __shared__ float s_pool[VN * EMB];
    int tid = threadIdx.x;
    int j = tid & 63, rq = tid >> 6;

    for (int i = tid; i < 16 * EMB; i += 256) s_w[i] = w[i];
    if (doPool) for (int i = tid; i < VN * EMB; i += 256) s_pool[i] = 0.f;
    float breg = b[j];
    __syncthreads();
    float wreg[16];
    #pragma unroll
    for (int k = 0; k < 16; k++) wreg[k] = s_w[k * EMB + j];

    int ntiles = (nrows + 31) / 32;
    for (int tile = blockIdx.x; tile < ntiles; tile += gridDim.x) {
        int base = tile * 32;
        __syncthreads();
        if (tid < 128) {
            int r = tid >> 2, k4 = tid & 3;
            int row = base + r;
            float4 v = (row < nrows) ? ((const float4*)feat)[(size_t)row * 4 + k4]
                                     : make_float4(0.f, 0.f, 0.f, 0.f);
            s_in[r][k4 * 4 + 0] = v.x; s_in[r][k4 * 4 + 1] = v.y;
            s_in[r][k4 * 4 + 2] = v.z; s_in[r][k4 * 4 + 3] = v.w;
        }
        if (doPool && tid < 32) {
            int row = base + tid;
            s_batch[tid] = (row < nrows) ? batch[row] : 0;
        }
        __syncthreads();
        #pragma unroll
        for (int s = 0; s < 8; s++) {
            int r = rq + s * 4;
            int row = base + r;
            if (row < nrows) {
                float a = breg;
                #pragma unroll
                for (int k = 0; k < 16; k++) a += s_in[r][k] * wreg[k];
                a = fmaxf(a, 0.f);
                if (out32) out32[(size_t)row * os32 + j] = a;
                if (out16) out16[(size_t)row * os16 + j] = __float2half_rn(a);
                if (doPool) atomicAdd(&s_pool[s_batch[r] * EMB + j], a);
            }
        }
    }
    if (doPool) {
        __syncthreads();
        for (int i = tid; i < VN * EMB; i += 256) atomicAdd(&g_poolA[i], s_pool[i]);
    }
}

// ---------------- VN update (consumes + re-zeros given pool buffer) ----------------
__global__ void k_vn(const float* __restrict__ w, const float* __restrict__ b,
                     float* __restrict__ pool) {
    int v = blockIdx.x, j = threadIdx.x;
    __shared__ float t[EMB];
    float cnt = g_cntvn[v];
    float vv = g_vn[v * EMB + j];
    t[j] = (pool[v * EMB + j] + cnt * vv) / fmaxf(cnt, 1.f) + vv;
    pool[v * EMB + j] = 0.f;
    __syncthreads();
    float acc = b[j];
    #pragma unroll
    for (int k = 0; k < EMB; k++) acc += t[k] * w[k * EMB + j];
    g_vn[v * EMB + j] = vv + fmaxf(acc, 0.f);
}

// =====================================================================
// Persistent fused gather + 3xTF32 mma conv kernels (fp16 cat storage)
// =====================================================================
#define CLD 68
#define DSMEM_NET  ((64 * CLD + 64 * CLD + VN * EMB + EMB) * 4)               // ~51 KB
#define DSMEM_NODE ((64 * CLD + 64 * CLD + EMB) * 4 + VN * EMB * 4)           // ~51.5 KB
#define CONV_GRID 592
#define NTILES_NET  ((MNET + 63) / 64)
#define NTILES_NODE ((NCELL + 63) / 64)

__device__ __forceinline__ void conv_mma_epilogue(
    float* As, float* Ws, const float* sb,
    int tid, long long row0, int nrows,
    float* __restrict__ f32out, int f32s4,
    uint2* __restrict__ f16out, int f16s, int f16o,
    float* s_pool, const int* __restrict__ batch)
{
    int warp = tid >> 5, lane = tid & 31;
    int gid = lane >> 2, tig = lane & 3;
    int mrow0 = (warp >> 1) * 16;
    int ncol0 = (warp & 1) * 32;

    float c[4][4];
    #pragma unroll
    for (int nt = 0; nt < 4; nt++)
        #pragma unroll
        for (int q = 0; q < 4; q++) c[nt][q] = 0.f;

    #pragma unroll
    for (int kk = 0; kk < 8; kk++) {
        int kb = kk * 8;
        uint32_t ah0, al0, ah1, al1, ah2, al2, ah3, al3;
        split_tf32(As[(mrow0 + gid) * CLD + kb + tig], ah0, al0);
        split_tf32(As[(mrow0 + gid + 8) * CLD + kb + tig], ah1, al1);
        split_tf32(As[(mrow0 + gid) * CLD + kb + tig + 4], ah2, al2);
        split_tf32(As[(mrow0 + gid + 8) * CLD + kb + tig + 4], ah3, al3);
        #pragma unroll
        for (int nt = 0; nt < 4; nt++) {
            int col = ncol0 + nt * 8 + gid;
            uint32_t bh0, bl0, bh1, bl1;
            split_tf32(Ws[(kb + tig) * CLD + col], bh0, bl0);
            split_tf32(Ws[(kb + tig + 4) * CLD + col], bh1, bl1);
            mma_tf32(c[nt], ah0, ah1, ah2, ah3, bh0, bh1);
            mma_tf32(c[nt], ah0, ah1, ah2, ah3, bl0, bl1);
            mma_tf32(c[nt], al0, al1, al2, al3, bh0, bh1);
        }
    }
    __syncthreads();
    #pragma unroll
    for (int nt = 0; nt < 4; nt++) {
        int col0 = ncol0 + nt * 8 + 2 * tig;
        float b0 = sb[col0], b1 = sb[col0 + 1];
        As[(mrow0 + gid) * CLD + col0]     = fmaxf(c[nt][0] + b0, 0.f);
        As[(mrow0 + gid) * CLD + col0 + 1] = fmaxf(c[nt][1] + b1, 0.f);
        As[(mrow0 + gid + 8) * CLD + col0]     = fmaxf(c[nt][2] + b0, 0.f);
        As[(mrow0 + gid + 8) * CLD + col0 + 1] = fmaxf(c[nt][3] + b1, 0.f);
    }
    __syncthreads();
    #pragma unroll
    for (int q = 0; q < 4; q++) {
        int idx = q * 256 + tid;
        int r = idx >> 4, c4 = idx & 15;
        long long row = row0 + r;
        if (row < nrows) {
            float4 v = *(const float4*)(As + r * CLD + c4 * 4);
            if (f32out) ((float4*)f32out)[row * f32s4 + c4] = v;
            union { __half2 h[2]; uint2 u; } pk;
            pk.h[0] = __floats2half2_rn(v.x, v.y);
            pk.h[1] = __floats2half2_rn(v.z, v.w);
            f16out[row * f16s + f16o + c4] = pk.u;
            if (s_pool) {
                int bb = batch[row];
                float* dst = s_pool + bb * EMB + c4 * 4;
                atomicAdd(dst + 0, v.x);
                atomicAdd(dst + 1, v.y);
                atomicAdd(dst + 2, v.z);
                atomicAdd(dst + 3, v.w);
            }
        }
    }
}

__global__ __launch_bounds__(256) void k_net_mma(
    const float* __restrict__ W, const float* __restrict__ b, int l, int writeF32) {
    extern __shared__ float sm[];
    float* As = sm;
    float* Ws = sm + 64 * CLD;
    float* vns = sm + 128 * CLD;
    float* sb = vns + VN * EMB;
    int tid = threadIdx.x;
    for (int i = tid; i < EMB * EMB; i += 256) Ws[(i >> 6) * CLD + (i & 63)] = W[i];
    for (int i = tid; i < VN * EMB; i += 256) vns[i] = g_vn[i];
    if (tid < EMB) sb[tid] = b[tid];

    int warp = tid >> 5, lane = tid & 31;
    const __half2* cat2h = (const __half2*)g_cat;
    const float2* net2 = (const float2*)g_net;
    const float2* vn2 = (const float2*)vns;
    int loff = l * 32;

    for (int tile = blockIdx.x; tile < NTILES_NET; tile += gridDim.x) {
        long long row0 = (long long)tile * 64;
        __syncthreads();
        int offl = 0;
        {
            long long idx = row0 + warp * 8 + lane;
            if (lane < 9) offl = g_off_net[(idx > MNET) ? MNET : idx];
        }
        for (int q = 0; q < 8; q++) {
            int r = warp * 8 + q;
            long long netid = row0 + r;
            int p0 = __shfl_sync(0xffffffffu, offl, q);
            int p1 = __shfl_sync(0xffffffffu, offl, q + 1);
            float2 acc = make_float2(0.f, 0.f);
            if (netid < MNET) {
                acc = net2[netid * 32 + lane];
                int p = p0;
                for (; p + 3 < p1; p += 4) {
                    int2 e0 = g_csr_net[p], e1 = g_csr_net[p + 1];
                    int2 e2 = g_csr_net[p + 2], e3 = g_csr_net[p + 3];
                    int n0 = e0.x & NODE_MASK, b0 = e0.x >> 19;
                    int n1 = e1.x & NODE_MASK, b1 = e1.x >> 19;
                    int n2 = e2.x & NODE_MASK, b2 = e2.x >> 19;
                    int n3 = e3.x & NODE_MASK, b3 = e3.x >> 19;
                    float2 v0 = __half22float2(cat2h[(size_t)n0 * 128 + loff + lane]);
                    float2 v1 = __half22float2(cat2h[(size_t)n1 * 128 + loff + lane]);
                    float2 v2 = __half22float2(cat2h[(size_t)n2 * 128 + loff + lane]);
                    float2 v3 = __half22float2(cat2h[(size_t)n3 * 128 + loff + lane]);
                    float2 u0 = vn2[b0 * 32 + lane];
                    float2 u1 = vn2[b1 * 32 + lane];
                    float2 u2 = vn2[b2 * 32 + lane];
                    float2 u3 = vn2[b3 * 32 + lane];
                    float w0 = __int_as_float(e0.y), w1 = __int_as_float(e1.y);
                    float w2 = __int_as_float(e2.y), w3 = __int_as_float(e3.y);
                    acc.x += w0 * (v0.x + u0.x) + w1 * (v1.x + u1.x)
                           + w2 * (v2.x + u2.x) + w3 * (v3.x + u3.x);
                    acc.y += w0 * (v0.y + u0.y) + w1 * (v1.y + u1.y)
                           + w2 * (v2.y + u2.y) + w3 * (v3.y + u3.y);
                }
                for (; p < p1; p++) {
                    int2 e0 = g_csr_net[p];
                    int n0 = e0.x & NODE_MASK, b0 = e0.x >> 19;
                    float2 v0 = __half22float2(cat2h[(size_t)n0 * 128 + loff + lane]);
                    float2 u0 = vn2[b0 * 32 + lane];
                    float w0 = __int_as_float(e0.y);
                    acc.x += w0 * (v0.x + u0.x);
                    acc.y += w0 * (v0.y + u0.y);
                }
            }
            *(float2*)(As + r * CLD + 2 * lane) = acc;
        }
        __syncthreads();
        conv_mma_epilogue(As, Ws, sb, tid, row0, MNET,
                          writeF32 ? (float*)g_net : nullptr, 16,
                          (uint2*)g_neth, 16, 0, nullptr, nullptr);
    }
}

__global__ __launch_bounds__(256) void k_node_mma(
    const float* __restrict__ W, const float* __restrict__ b,
    const int* __restrict__ batch, int l, int doPool) {
    extern __shared__ float sm[];
    float* As = sm;
    float* Ws = sm + 64 * CLD;
    float* sb = sm + 128 * CLD;
    float* s_pool = sm + 128 * CLD + EMB;
    int tid = threadIdx.x;
    for (int i = tid; i < EMB * EMB; i += 256) Ws[(i >> 6) * CLD + (i & 63)] = W[i];
    if (tid < EMB) sb[tid] = b[tid];
    if (doPool) for (int i = tid; i < VN * EMB; i += 256) s_pool[i] = 0.f;

    int warp = tid >> 5, lane = tid & 31;
    const __half2* cat2h = (const __half2*)g_cat;
    const __half2* neth2 = (const __half2*)g_neth;
    const float2* vn2 = (const float2*)g_vn;
    float* poolArg = doPool ? s_pool : nullptr;
    int loff = l * 32;

    for (int tile = blockIdx.x; tile < NTILES_NODE; tile += gridDim.x) {
        long long row0 = (long long)tile * 64;
        __syncthreads();
        int offl = 0;
        {
            long long idx = row0 + warp * 8 + lane;
            if (lane < 9) offl = g_off_node[(idx > NCELL) ? NCELL : idx];
        }
        for (int q = 0; q < 8; q++) {
            int r = warp * 8 + q;
            long long node = row0 + r;
            int p0 = __shfl_sync(0xffffffffu, offl, q);
            int p1 = __shfl_sync(0xffffffffu, offl, q + 1);
            float2 acc = make_float2(0.f, 0.f);
            if (node < NCELL) {
                int bb = batch[node];
                float2 v = __half22float2(cat2h[node * 128 + loff + lane]);
                float2 u = vn2[bb * 32 + lane];
                acc.x = v.x + u.x; acc.y = v.y + u.y;
                int p = p0;
                for (; p + 3 < p1; p += 4) {
                    int2 e0 = g_csr_node[p], e1 = g_csr_node[p + 1];
                    int2 e2 = g_csr_node[p + 2], e3 = g_csr_node[p + 3];
                    float2 v0 = __half22float2(neth2[(size_t)e0.x * 32 + lane]);
                    float2 v1 = __half22float2(neth2[(size_t)e1.x * 32 + lane]);
                    float2 v2 = __half22float2(neth2[(size_t)e2.x * 32 + lane]);
                    float2 v3 = __half22float2(neth2[(size_t)e3.x * 32 + lane]);
                    float w0 = __int_as_float(e0.y), w1 = __int_as_float(e1.y);
                    float w2 = __int_as_float(e2.y), w3 = __int_as_float(e3.y);
                    acc.x += w0 * v0.x + w1 * v1.x + w2 * v2.x + w3 * v3.x;
                    acc.y += w0 * v0.y + w1 * v1.y + w2 * v2.y + w3 * v3.y;
                }
                for (; p < p1; p++) {
                    int2 e0 = g_csr_node[p];
                    float2 v0 = __half22float2(neth2[(size_t)e0.x * 32 + lane]);
                    float w0 = __int_as_float(e0.y);
                    acc.x += w0 * v0.x; acc.y += w0 * v0.y;
                }
            }
            *(float2*)(As + r * CLD + 2 * lane) = acc;
        }
        __syncthreads();
        conv_mma_epilogue(As, Ws, sb, tid, row0, NCELL,
                          nullptr, 0,
                          (uint2*)g_cat, 64, (l + 1) * 16, poolArg, batch);
    }
    if (doPool) {
        __syncthreads();
        for (int i = tid; i < VN * EMB; i += 256) atomicAdd(&g_poolB[i], s_pool[i]);
    }
}

// ---------------- head: 128 rows x 256 cols, 512 threads (fp16 cat input) ----------------
#define AS_LD 68
#define BS_LD 260
#define HS_LD 260
#define DSMEM_HEAD (128 * HS_LD * 4)

__global__ __launch_bounds__(512) void k_head_mma(
    const float* __restrict__ fc1w, const float* __restrict__ fc1b,
    const float* __restrict__ fc2w, const float* __restrict__ fc2b,
    const float* __restrict__ outw, const float* __restrict__ outb,
    const __half* __restrict__ cat,
    float* __restrict__ nodes_out, float* __restrict__ ret_out) {
    extern __shared__ float sm[];
    float* As = sm;
    float* Bs = sm + 128 * AS_LD;
    float* Hs = sm;
    __shared__ float s_ow[CATD];
    __shared__ float s_fc2[8 * 256];
    __shared__ float rpart4[128][4];

    int tid = threadIdx.x;
    int warp = tid >> 5, lane = tid & 31;
    int gid = lane >> 2, tig = lane & 3;
    int mrow0 = (warp >> 2) * 32;
    int ncol0 = (warp & 3) * 64;
    size_t n0 = (size_t)blockIdx.x * 128;

    if (tid < CATD) s_ow[tid] = outw[tid];
    for (int i = tid; i < 2048; i += 512) {
        int o = i >> 8, jj = i & 255;
        s_fc2[o * 256 + jj] = fc2w[jj * 8 + o];
    }
    { int r = tid >> 2, q = tid & 3; rpart4[r][q] = 0.f; }

    float c[2][8][4];
    #pragma unroll
    for (int mf = 0; mf < 2; mf++)
        #pragma unroll
        for (int nt = 0; nt < 8; nt++)
            #pragma unroll
            for (int q = 0; q < 4; q++) c[mf][nt][q] = 0.f;

    const uint2* cat4h = (const uint2*)cat;   // 4 halves per uint2, row stride 64
    for (int kc = 0; kc < 4; kc++) {
        __syncthreads();
        #pragma unroll
        for (int q = 0; q < 4; q++) {
            int idx = q * 512 + tid;
            int r = idx >> 4, k4 = idx & 15;
            size_t row = n0 + r;
            float4 v;
            if (row < NCELL) {
                uint2 h = cat4h[row * 64 + kc * 16 + k4];
                float2 a0 = __half22float2(*(__half2*)&h.x);
                float2 a1 = __half22float2(*(__half2*)&h.y);
                v = make_float4(a0.x, a0.y, a1.x, a1.y);
            } else v = make_float4(0.f, 0.f, 0.f, 0.f);
            *(float4*)(As + r * AS_LD + k4 * 4) = v;
        }
        #pragma unroll
        for (int q = 0; q < 8; q++) {
            int idx = q * 512 + tid;
            int r = idx >> 6, j4 = idx & 63;
            float4 v = *(const float4*)(fc1w + (size_t)(kc * 64 + r) * 256 + j4 * 4);
            *(float4*)(Bs + r * BS_LD + j4 * 4) = v;
        }
        __syncthreads();
        {
            int r = tid >> 2, q = tid & 3;
            float a = 0.f;
            #pragma unroll
            for (int kk = 0; kk < 16; kk++)
                a += As[r * AS_LD + q * 16 + kk] * s_ow[kc * 64 + q * 16 + kk];
            rpart4[r][q] += a;
        }
        #pragma unroll
        for (int kk = 0; kk < 8; kk++) {
            int kb = kk * 8;
            uint32_t a[2][4];
            #pragma unroll
            for (int mf = 0; mf < 2; mf++) {
                int rb = mrow0 + mf * 16;
                a[mf][0] = f2tf32(As[(rb + gid) * AS_LD + kb + tig]);
                a[mf][1] = f2tf32(As[(rb + gid + 8) * AS_LD + kb + tig]);
                a[mf][2] = f2tf32(As[(rb + gid) * AS_LD + kb + tig + 4]);
                a[mf][3] = f2tf32(As[(rb + gid + 8) * AS_LD + kb + tig + 4]);
            }
            #pragma unroll
            for (int nt = 0; nt < 8; nt++) {
                int col = ncol0 + nt * 8 + gid;
                uint32_t b0 = f2tf32(Bs[(kb + tig) * BS_LD + col]);
                uint32_t b1 = f2tf32(Bs[(kb + tig + 4) * BS_LD + col]);
                mma_tf32(c[0][nt], a[0][0], a[0][1], a[0][2], a[0][3], b0, b1);
                mma_tf32(c[1][nt], a[1][0], a[1][1], a[1][2], a[1][3], b0, b1);
            }
        }
    }
    __syncthreads();
    #pragma unroll
    for (int mf = 0; mf < 2; mf++) {
        int rb = mrow0 + mf * 16;
        #pragma unroll
        for (int nt = 0; nt < 8; nt++) {
            int col0 = ncol0 + nt * 8 + 2 * tig;
            float bb0 = fc1b[col0], bb1 = fc1b[col0 + 1];
            Hs[(rb + gid) * HS_LD + col0]     = fmaxf(c[mf][nt][0] + bb0, 0.f);
            Hs[(rb + gid) * HS_LD + col0 + 1] = fmaxf(c[mf][nt][1] + bb1, 0.f);
            Hs[(rb + gid + 8) * HS_LD + col0]     = fmaxf(c[mf][nt][2] + bb0, 0.f);
            Hs[(rb + gid + 8) * HS_LD + col0 + 1] = fmaxf(c[mf][nt][3] + bb1, 0.f);
        }
    }
    __syncthreads();
    #pragma unroll
    for (int pp = 0; pp < 2; pp++) {
        int p = tid + pp * 512;
        int r = p >> 3, o = p & 7;
        size_t row = n0 + r;
        float a = fc2b[o];
        const float4* h4 = (const float4*)(Hs + r * HS_LD);
        const float4* w4 = (const float4*)(s_fc2 + o * 256);
        #pragma unroll 8
        for (int jj = 0; jj < 64; jj++) {
            float4 h = h4[jj], w = w4[jj];
            a += h.x * w.x + h.y * w.y + h.z * w.z + h.w * w.w;
        }
        if (row < NCELL) nodes_out[row * OUTD + o] = fmaxf(a, 0.f);
    }
    if (tid < 128) {
        size_t row = n0 + tid;
        if (row < NCELL) {
            float s = outb[0] + rpart4[tid][0] + rpart4[tid][1] + rpart4[tid][2] + rpart4[tid][3];
            ret_out[row] = s;
        }
    }
}

// ---------------- launch ----------------
static inline int cdiv(long long a, long long b) { return (int)((a + b - 1) / b); }

extern "C" void kernel_launch(void* const* d_in, const int* in_sizes, int n_in,
                              void* d_out, int out_size) {
    const float* node_f     = (const float*)d_in[0];
    const float* net_f      = (const float*)d_in[1];
    const int*   sink_node  = (const int*)d_in[2];
    const int*   sink_net   = (const int*)d_in[3];
    const int*   src_node   = (const int*)d_in[4];
    const int*   src_net    = (const int*)d_in[5];
    const int*   batch      = (const int*)d_in[6];
    const float* w_node     = (const float*)d_in[8];
    const float* b_node     = (const float*)d_in[9];
    const float* w_net      = (const float*)d_in[10];
    const float* b_net      = (const float*)d_in[11];
    const float* vn_emb     = (const float*)d_in[12];
    const float* vn_mlp_w   = (const float*)d_in[13];
    const float* vn_mlp_b   = (const float*)d_in[14];
    const float* conv_net_w = (const float*)d_in[15];
    const float* conv_net_b = (const float*)d_in[16];
    const float* conv_node_w= (const float*)d_in[17];
    const float* conv_node_b= (const float*)d_in[18];
    const float* fc1_w      = (const float*)d_in[19];
    const float* fc1_b      = (const float*)d_in[20];
    const float* fc2_w      = (const float*)d_in[21];
    const float* fc2_b      = (const float*)d_in[22];
    const float* out_w      = (const float*)d_in[23];
    const float* out_b      = (const float*)d_in[24];

    static bool attr_done = false;
    if (!attr_done) {
        cudaFuncSetAttribute(k_head_mma, cudaFuncAttributeMaxDynamicSharedMemorySize, DSMEM_HEAD);
        cudaFuncSetAttribute(k_net_mma, cudaFuncAttributeMaxDynamicSharedMemorySize, DSMEM_NET);
        cudaFuncSetAttribute(k_node_mma, cudaFuncAttributeMaxDynamicSharedMemorySize, DSMEM_NODE);
        attr_done = true;
    }

    float *p_net, *p_poolA, *p_poolB;
    __half *p_cat;
    cudaGetSymbolAddress((void**)&p_cat, g_cat);
    cudaGetSymbolAddress((void**)&p_net, g_net);
    cudaGetSymbolAddress((void**)&p_poolA, g_poolA);
    cudaGetSymbolAddress((void**)&p_poolB, g_poolB);

    // setup
    k_zero_all<<<cdiv(NCELL, 256), 256>>>();
    k_count<<<cdiv(EKE, 256), 256>>>(sink_node, sink_net, src_net);
    k_prep<<<cdiv(NCELL, 256), 256>>>(batch, vn_emb);
    k_embed<<<EMB_GRID, 256>>>(node_f, w_node, b_node, nullptr, 0, p_cat, CATD,
                               NCELL, 1, batch);
    k_embed<<<EMB_GRID, 256>>>(net_f, w_net, b_net, p_net, EMB, nullptr, 0,
                               MNET, 0, nullptr);
    {
        int nb = cdiv(SCAN_TOT, 1024);
        k_scan1<<<nb, 256>>>();
        k_scan2<<<1, 1024>>>(nb);
        k_scan3<<<nb, 256>>>();
    }
    k_scat<<<cdiv(EKE, 256), 256>>>(sink_node, sink_net, src_node, src_net, batch);

    // layers; pool(0) fused into node embed (->poolA), pool(1) fused into node_mma(0) (->poolB)
    for (int l = 0; l < NL; l++) {
        k_net_mma<<<CONV_GRID, 256, DSMEM_NET>>>(conv_net_w + l * 4096, conv_net_b + l * 64,
                                                 l, (l < NL - 1) ? 1 : 0);
        k_node_mma<<<CONV_GRID, 256, DSMEM_NODE>>>(conv_node_w + l * 4096, conv_node_b + l * 64,
                                                   batch, l, (l == 0) ? 1 : 0);
        if (l < NL - 1)
            k_vn<<<VN, EMB>>>(vn_mlp_w + l * 4096, vn_mlp_b + l * 64,
                              (l == 0) ? p_poolA : p_poolB);
    }

    // head
    float* nodes_out = (float*)d_out;
    float* ret_out = (float*)d_out + (size_t)NCELL * OUTD;
    k_head_mma<<<cdiv(NCELL, 128), 512, DSMEM_HEAD>>>(fc1_w, fc1_b, fc2_w, fc2_b,
                                                      out_w, out_b, p_cat, nodes_out, ret_out);
}